// round 4
// baseline (speedup 1.0000x reference)
#include <cuda_runtime.h>
#include <cuda_fp16.h>
#include <math.h>

#define NN 50000
#define NE 1600000
#define NB 196          // ceil(NN/256)

// ---------------- scratch -----------------------------------------------------
__device__ __half d_Qh[NN * 256];       // [n][pair(16)][c(16)] q pre-scaled by 0.25*log2e
__device__ __half d_KV[NN * 512];       // [n][pair(16)][K 16 | V 16] fp16
__device__ float  d_H[NN * 256];        // skip first, then h (post-ELU); flat = band*32+h*16+c
__device__ float  d_HW[NN * 32];
__device__ float4 d_csr[NE];            // {src(int bits), ax, ay, dis[src]*ay}
__device__ int    d_count[NN];
__device__ int    d_cursor[NN];
__device__ int    d_offsets[NN + 1];
__device__ int    d_bsum[NB];
__device__ int    d_boff[NB];
__device__ float  d_degw[NN];
__device__ float  d_dis[NN];

__device__ __forceinline__ float ex2f(float x) {
    float y; asm("ex2.approx.f32 %0, %1;" : "=f"(y) : "f"(x)); return y;
}
__device__ __forceinline__ __half2 h2(unsigned u) { return *(__half2*)&u; }

// ---------------- CSR build ---------------------------------------------------
__global__ void zero_kernel() {
    int i = blockIdx.x * blockDim.x + threadIdx.x;
    if (i < NN) { d_count[i] = 0; d_cursor[i] = 0; d_degw[i] = 0.f; }
}

__global__ void hist_kernel(const int* __restrict__ ei, const float* __restrict__ ea) {
    int e = blockIdx.x * blockDim.x + threadIdx.x;
    if (e < NE) {
        int dst = ei[NE + e];
        atomicAdd(&d_count[dst], 1);
        atomicAdd(&d_degw[dst], ea[2 * e + 1]);
    }
}

// pass A: per-256-chunk exclusive scan + chunk totals
__global__ void scanA_kernel() {
    __shared__ int ws[8];
    int tid = threadIdx.x, lane = tid & 31, wid = tid >> 5;
    int i = blockIdx.x * 256 + tid;
    int v = (i < NN) ? d_count[i] : 0;
    int s = v;
    #pragma unroll
    for (int off = 1; off < 32; off <<= 1) {
        int t = __shfl_up_sync(0xffffffffu, s, off);
        if (lane >= off) s += t;
    }
    if (lane == 31) ws[wid] = s;
    __syncthreads();
    if (tid < 8) {
        int t = ws[tid];
        #pragma unroll
        for (int off = 1; off < 8; off <<= 1) {
            int u = __shfl_up_sync(0xffu, t, off);
            if (tid >= off) t += u;
        }
        ws[tid] = t;
    }
    __syncthreads();
    int wexcl = wid ? ws[wid - 1] : 0;
    if (i < NN) d_offsets[i] = wexcl + s - v;
    if (tid == 0) d_bsum[blockIdx.x] = ws[7];
}

// pass B: scan chunk totals (NB <= 256) in one block
__global__ void scanB_kernel() {
    __shared__ int ws[8];
    int tid = threadIdx.x, lane = tid & 31, wid = tid >> 5;
    int v = (tid < NB) ? d_bsum[tid] : 0;
    int s = v;
    #pragma unroll
    for (int off = 1; off < 32; off <<= 1) {
        int t = __shfl_up_sync(0xffffffffu, s, off);
        if (lane >= off) s += t;
    }
    if (lane == 31) ws[wid] = s;
    __syncthreads();
    if (tid < 8) {
        int t = ws[tid];
        #pragma unroll
        for (int off = 1; off < 8; off <<= 1) {
            int u = __shfl_up_sync(0xffu, t, off);
            if (tid >= off) t += u;
        }
        ws[tid] = t;
    }
    __syncthreads();
    int wexcl = wid ? ws[wid - 1] : 0;
    if (tid < NB) d_boff[tid] = wexcl + s - v;
}

// pass C: add chunk offsets; also dis = rsqrt(degw + 2)
__global__ void scanC_kernel() {
    int i = blockIdx.x * 256 + threadIdx.x;
    if (i < NN) {
        d_offsets[i] += d_boff[blockIdx.x];
        d_dis[i] = rsqrtf(d_degw[i] + 2.0f);
    }
    if (i == 0) d_offsets[NN] = NE;
}

__global__ void scatter_kernel(const int* __restrict__ ei, const float* __restrict__ ea) {
    int e = blockIdx.x * blockDim.x + threadIdx.x;
    if (e < NE) {
        int src = ei[e], dst = ei[NE + e];
        int pos = d_offsets[dst] + atomicAdd(&d_cursor[dst], 1);
        float ax = ea[2 * e], ay = ea[2 * e + 1];
        float4 pk;
        pk.x = __int_as_float(src);
        pk.y = ax;
        pk.z = ay;
        pk.w = d_dis[src] * ay;
        d_csr[pos] = pk;
    }
}

// ---------------- QKV + skip precompute ---------------------------------------
__global__ void qkv_kernel(const float* __restrict__ x,
                           const float* __restrict__ Wq, const float* __restrict__ bq,
                           const float* __restrict__ Wk, const float* __restrict__ bk,
                           const float* __restrict__ Wv, const float* __restrict__ bv,
                           const float* __restrict__ Wsk, const float* __restrict__ bsk) {
    int lane = threadIdx.x & 31;
    int warp = (blockIdx.x * blockDim.x + threadIdx.x) >> 5;
    int nwarps = (gridDim.x * blockDim.x) >> 5;
    float wq[8], wk[8], wv[8], ws[8];
    #pragma unroll
    for (int i = 0; i < 8; i++) {
        wq[i] = Wq[i * 32 + lane];
        wk[i] = Wk[i * 32 + lane];
        wv[i] = Wv[i * 32 + lane];
        ws[i] = Wsk[i * 32 + lane];
    }
    float bqv = bq[lane], bkv = bk[lane], bvv = bv[lane], bsv = bsk[lane];
    const float QS = 0.25f * 1.4426950408889634f;  // 1/sqrt(16) * log2(e)
    int h = lane >> 4, c = lane & 15;

    for (int n = warp; n < NN; n += nwarps) {
        float x0 = x[n * 64 + lane];
        float x1 = x[n * 64 + 32 + lane];
        #pragma unroll
        for (int b = 0; b < 8; b++) {
            float aq = bqv, ak = bkv, av = bvv, asv = bsv;
            #pragma unroll
            for (int i = 0; i < 8; i++) {
                const int f = b * 8 + i;
                float xv = __shfl_sync(0xffffffffu, (f < 32) ? x0 : x1, f & 31);
                aq += xv * wq[i]; ak += xv * wk[i]; av += xv * wv[i]; asv += xv * ws[i];
            }
            int pairIdx = b * 2 + h;
            d_Qh[n * 256 + pairIdx * 16 + c] = __float2half(aq * QS);
            d_KV[n * 512 + pairIdx * 32 + c]      = __float2half(ak);
            d_KV[n * 512 + pairIdx * 32 + 16 + c] = __float2half(av);
            d_H[n * 256 + pairIdx * 16 + c] = asv;   // flat == band*32+h*16+c
        }
    }
}

// ---------------- attention ---------------------------------------------------
// 2 warps per dst (sub 0/1); lane owns one (band,head) pair; half-warps split
// edges -> 4 streams/dst; 2-edge unroll per stream -> 8 edges in flight per dst.
__device__ __forceinline__ __half2 dot8(uint4 a, uint4 b, const __half2* q) {
    __half2 d = __float2half2_rn(0.f);
    d = __hfma2(q[0], h2(a.x), d);
    d = __hfma2(q[1], h2(a.y), d);
    d = __hfma2(q[2], h2(a.z), d);
    d = __hfma2(q[3], h2(a.w), d);
    d = __hfma2(q[4], h2(b.x), d);
    d = __hfma2(q[5], h2(b.y), d);
    d = __hfma2(q[6], h2(b.z), d);
    d = __hfma2(q[7], h2(b.w), d);
    return d;
}

__global__ void __launch_bounds__(256, 2) attn_kernel(const float* __restrict__ We) {
    __shared__ float sm[4][16][20];   // [slot][pair][16 acc + sax + say + z]
    int tid = threadIdx.x, lane = tid & 31, wid = tid >> 5;
    int slot = wid >> 1, sub = wid & 1;
    int dst = blockIdx.x * 4 + slot;
    int pair = lane & 15, hf = lane >> 4;
    int hoff = (pair & 1) << 4;

    __half2 w0h[8], w1h[8], q[8];
    #pragma unroll
    for (int i = 0; i < 8; i++) {
        w0h[i] = __floats2half2_rn(We[hoff + 2 * i],      We[hoff + 2 * i + 1]);
        w1h[i] = __floats2half2_rn(We[32 + hoff + 2 * i], We[32 + hoff + 2 * i + 1]);
    }
    {
        const uint4* Qp = (const uint4*)&d_Qh[dst * 256 + pair * 16];
        uint4 qa = Qp[0], qb = Qp[1];
        q[0] = h2(qa.x); q[1] = h2(qa.y); q[2] = h2(qa.z); q[3] = h2(qa.w);
        q[4] = h2(qb.x); q[5] = h2(qb.y); q[6] = h2(qb.z); q[7] = h2(qb.w);
    }
    float qw0, qw1;
    {
        __half2 t0 = __float2half2_rn(0.f), t1 = __float2half2_rn(0.f);
        #pragma unroll
        for (int i = 0; i < 8; i++) {
            t0 = __hfma2(q[i], w0h[i], t0);
            t1 = __hfma2(q[i], w1h[i], t1);
        }
        float2 f0 = __half22float2(t0), f1 = __half22float2(t1);
        qw0 = f0.x + f0.y; qw1 = f1.x + f1.y;
    }

    __half2 acch[8];
    #pragma unroll
    for (int i = 0; i < 8; i++) acch[i] = __float2half2_rn(0.f);
    float sax = 0.f, say = 0.f, z = 0.f;

    int start = d_offsets[dst], end = d_offsets[dst + 1];
    for (int e = start + sub * 2 + hf; e < end; e += 8) {
        int eB = e + 4;
        bool hasB = (eB < end);
        float4 pkA = d_csr[e];
        float4 pkB = d_csr[hasB ? eB : e];
        int srcA = __float_as_int(pkA.x);
        int srcB = __float_as_int(pkB.x);
        const uint4* pA = (const uint4*)&d_KV[srcA * 512 + pair * 32];
        uint4 ka0 = pA[0], ka1 = pA[1], va0 = pA[2], va1 = pA[3];
        const uint4* pB = (const uint4*)&d_KV[srcB * 512 + pair * 32];
        uint4 kb0 = pB[0], kb1 = pB[1], vb0 = pB[2], vb1 = pB[3];

        float2 dA = __half22float2(dot8(ka0, ka1, q));
        float dotA = dA.x + dA.y + pkA.y * qw0 + pkA.z * qw1;
        float pAf = ex2f(dotA);
        float2 dB = __half22float2(dot8(kb0, kb1, q));
        float dotB = dB.x + dB.y + pkB.y * qw0 + pkB.z * qw1;
        float pBf = hasB ? ex2f(dotB) : 0.f;

        z += pAf + pBf;
        sax = fmaf(pAf, pkA.y, sax); sax = fmaf(pBf, pkB.y, sax);
        say = fmaf(pAf, pkA.z, say); say = fmaf(pBf, pkB.z, say);

        __half2 pA2 = __float2half2_rn(pAf);
        __half2 pB2 = __float2half2_rn(pBf);
        acch[0] = __hfma2(pA2, h2(va0.x), acch[0]);
        acch[1] = __hfma2(pA2, h2(va0.y), acch[1]);
        acch[2] = __hfma2(pA2, h2(va0.z), acch[2]);
        acch[3] = __hfma2(pA2, h2(va0.w), acch[3]);
        acch[4] = __hfma2(pA2, h2(va1.x), acch[4]);
        acch[5] = __hfma2(pA2, h2(va1.y), acch[5]);
        acch[6] = __hfma2(pA2, h2(va1.z), acch[6]);
        acch[7] = __hfma2(pA2, h2(va1.w), acch[7]);
        acch[0] = __hfma2(pB2, h2(vb0.x), acch[0]);
        acch[1] = __hfma2(pB2, h2(vb0.y), acch[1]);
        acch[2] = __hfma2(pB2, h2(vb0.z), acch[2]);
        acch[3] = __hfma2(pB2, h2(vb0.w), acch[3]);
        acch[4] = __hfma2(pB2, h2(vb1.x), acch[4]);
        acch[5] = __hfma2(pB2, h2(vb1.y), acch[5]);
        acch[6] = __hfma2(pB2, h2(vb1.z), acch[6]);
        acch[7] = __hfma2(pB2, h2(vb1.w), acch[7]);
    }

    float accf[16];
    #pragma unroll
    for (int i = 0; i < 8; i++) {
        float2 t = __half22float2(acch[i]);
        accf[2 * i] = t.x; accf[2 * i + 1] = t.y;
    }
    z   += __shfl_xor_sync(0xffffffffu, z, 16);
    sax += __shfl_xor_sync(0xffffffffu, sax, 16);
    say += __shfl_xor_sync(0xffffffffu, say, 16);
    #pragma unroll
    for (int c = 0; c < 16; c++) accf[c] += __shfl_xor_sync(0xffffffffu, accf[c], 16);

    if (sub == 1 && lane < 16) {
        #pragma unroll
        for (int c = 0; c < 16; c++) sm[slot][lane][c] = accf[c];
        sm[slot][lane][16] = sax; sm[slot][lane][17] = say; sm[slot][lane][18] = z;
    }
    __syncthreads();
    if (sub == 0 && lane < 16) {
        #pragma unroll
        for (int c = 0; c < 16; c++) accf[c] += sm[slot][lane][c];
        sax += sm[slot][lane][16]; say += sm[slot][lane][17]; z += sm[slot][lane][18];
        float rz = (z > 0.f) ? 1.0f / z : 0.f;
        float* Hp = &d_H[dst * 256 + pair * 16];
        float o[16];
        #pragma unroll
        for (int c = 0; c < 16; c++) {
            float w0 = We[hoff + c], w1 = We[32 + hoff + c];
            float a = accf[c] + sax * w0 + say * w1;
            float t = fmaf(a, rz, Hp[c]);
            o[c] = (t > 0.f) ? t : 0.1f * (__expf(t) - 1.0f);
        }
        float4* Op = (float4*)Hp;
        Op[0] = make_float4(o[0], o[1], o[2], o[3]);
        Op[1] = make_float4(o[4], o[5], o[6], o[7]);
        Op[2] = make_float4(o[8], o[9], o[10], o[11]);
        Op[3] = make_float4(o[12], o[13], o[14], o[15]);
    }
}

// ---------------- hw = h @ Wg -------------------------------------------------
__global__ void hw_kernel(const float* __restrict__ Wg) {
    __shared__ float wgs[256 * 32];
    for (int idx = threadIdx.x; idx < 8192; idx += blockDim.x)
        wgs[idx] = Wg[idx];
    __syncthreads();
    int lane = threadIdx.x & 31;
    int warp = (blockIdx.x * blockDim.x + threadIdx.x) >> 5;
    int nwarps = (gridDim.x * blockDim.x) >> 5;
    for (int n = warp; n < NN; n += nwarps) {
        const float4* Hp = (const float4*)&d_H[n * 256];
        float a = 0.f;
        #pragma unroll
        for (int c = 0; c < 64; c++) {
            float4 hv = Hp[c];
            a += hv.x * wgs[(4 * c + 0) * 32 + lane];
            a += hv.y * wgs[(4 * c + 1) * 32 + lane];
            a += hv.z * wgs[(4 * c + 2) * 32 + lane];
            a += hv.w * wgs[(4 * c + 3) * 32 + lane];
        }
        d_HW[n * 32 + lane] = a;
    }
}

// ---------------- final normalized propagation --------------------------------
__global__ void final_kernel(const float* __restrict__ bg, float* __restrict__ out) {
    int lane = threadIdx.x & 31;
    int dst = (blockIdx.x * blockDim.x + threadIdx.x) >> 5;
    if (dst >= NN) return;
    float dd = d_dis[dst];
    float acc = 2.0f * dd * d_HW[dst * 32 + lane];  // self loop
    int start = d_offsets[dst], end = d_offsets[dst + 1];
    int t = start;
    for (; t + 1 < end; t += 2) {
        float4 a = d_csr[t];
        float4 b = d_csr[t + 1];
        float va = d_HW[__float_as_int(a.x) * 32 + lane];
        float vb = d_HW[__float_as_int(b.x) * 32 + lane];
        acc = fmaf(a.w, va, acc);
        acc = fmaf(b.w, vb, acc);
    }
    if (t < end) {
        float4 a = d_csr[t];
        acc = fmaf(a.w, d_HW[__float_as_int(a.x) * 32 + lane], acc);
    }
    out[dst * 32 + lane] = bg[lane] + dd * acc;
}

// ---------------- launch -----------------------------------------------------
extern "C" void kernel_launch(void* const* d_in, const int* in_sizes, int n_in,
                              void* d_out, int out_size) {
    const float* x   = (const float*)d_in[0];
    const float* ea  = (const float*)d_in[1];
    const float* Wq  = (const float*)d_in[2];
    const float* bq  = (const float*)d_in[3];
    const float* Wk  = (const float*)d_in[4];
    const float* bk  = (const float*)d_in[5];
    const float* Wv  = (const float*)d_in[6];
    const float* bv  = (const float*)d_in[7];
    const float* We  = (const float*)d_in[8];
    const float* Wsk = (const float*)d_in[9];
    const float* bsk = (const float*)d_in[10];
    const float* Wg  = (const float*)d_in[11];
    const float* bg  = (const float*)d_in[12];
    const int*   ei  = (const int*)d_in[13];
    float* out = (float*)d_out;

    zero_kernel<<<(NN + 255) / 256, 256>>>();
    hist_kernel<<<(NE + 255) / 256, 256>>>(ei, ea);
    scanA_kernel<<<NB, 256>>>();
    scanB_kernel<<<1, 256>>>();
    scanC_kernel<<<NB, 256>>>();
    scatter_kernel<<<(NE + 255) / 256, 256>>>(ei, ea);
    qkv_kernel<<<400, 256>>>(x, Wq, bq, Wk, bk, Wv, bv, Wsk, bsk);
    attn_kernel<<<(NN + 3) / 4, 256>>>(We);
    hw_kernel<<<296, 256>>>(Wg);
    final_kernel<<<(NN * 32 + 255) / 256, 256>>>(bg, out);
}

// round 5
// speedup vs baseline: 1.0669x; 1.0669x over previous
#include <cuda_runtime.h>
#include <cuda_fp16.h>
#include <math.h>

#define NN 50000
#define NE 1600000
#define NB 196          // ceil(NN/256)

// ---------------- scratch -----------------------------------------------------
__device__ __half d_Qh[NN * 256];       // [n][pair(16)][c(16)] q pre-scaled by 0.25*log2e
__device__ __half d_KV[NN * 512];       // [n][pair(16)][K 16 | V 16] fp16
__device__ float  d_H[NN * 256];        // skip first, then h (post-ELU); flat = band*32+h*16+c
__device__ float  d_HW[NN * 32];
__device__ float4 d_csr[NE];            // {src(int bits), ax, ay, dis[src]*ay}
__device__ int    d_count[NN];
__device__ int    d_cursor[NN];
__device__ int    d_offsets[NN + 1];
__device__ int    d_bsum[NB];
__device__ int    d_boff[NB];
__device__ float  d_degw[NN];
__device__ float  d_dis[NN];

__device__ __forceinline__ float ex2f(float x) {
    float y; asm("ex2.approx.f32 %0, %1;" : "=f"(y) : "f"(x)); return y;
}
__device__ __forceinline__ __half2 h2(unsigned u) { return *(__half2*)&u; }

// ---------------- CSR build ---------------------------------------------------
__global__ void zero_kernel() {
    int i = blockIdx.x * blockDim.x + threadIdx.x;
    if (i < NN) { d_count[i] = 0; d_cursor[i] = 0; d_degw[i] = 0.f; }
}

__global__ void hist_kernel(const int* __restrict__ ei, const float* __restrict__ ea) {
    int e = blockIdx.x * blockDim.x + threadIdx.x;
    if (e < NE) {
        int dst = ei[NE + e];
        atomicAdd(&d_count[dst], 1);
        atomicAdd(&d_degw[dst], ea[2 * e + 1]);
    }
}

__global__ void scanA_kernel() {
    __shared__ int ws[8];
    int tid = threadIdx.x, lane = tid & 31, wid = tid >> 5;
    int i = blockIdx.x * 256 + tid;
    int v = (i < NN) ? d_count[i] : 0;
    int s = v;
    #pragma unroll
    for (int off = 1; off < 32; off <<= 1) {
        int t = __shfl_up_sync(0xffffffffu, s, off);
        if (lane >= off) s += t;
    }
    if (lane == 31) ws[wid] = s;
    __syncthreads();
    if (tid < 8) {
        int t = ws[tid];
        #pragma unroll
        for (int off = 1; off < 8; off <<= 1) {
            int u = __shfl_up_sync(0xffu, t, off);
            if (tid >= off) t += u;
        }
        ws[tid] = t;
    }
    __syncthreads();
    int wexcl = wid ? ws[wid - 1] : 0;
    if (i < NN) d_offsets[i] = wexcl + s - v;
    if (tid == 0) d_bsum[blockIdx.x] = ws[7];
}

__global__ void scanB_kernel() {
    __shared__ int ws[8];
    int tid = threadIdx.x, lane = tid & 31, wid = tid >> 5;
    int v = (tid < NB) ? d_bsum[tid] : 0;
    int s = v;
    #pragma unroll
    for (int off = 1; off < 32; off <<= 1) {
        int t = __shfl_up_sync(0xffffffffu, s, off);
        if (lane >= off) s += t;
    }
    if (lane == 31) ws[wid] = s;
    __syncthreads();
    if (tid < 8) {
        int t = ws[tid];
        #pragma unroll
        for (int off = 1; off < 8; off <<= 1) {
            int u = __shfl_up_sync(0xffu, t, off);
            if (tid >= off) t += u;
        }
        ws[tid] = t;
    }
    __syncthreads();
    int wexcl = wid ? ws[wid - 1] : 0;
    if (tid < NB) d_boff[tid] = wexcl + s - v;
}

__global__ void scanC_kernel() {
    int i = blockIdx.x * 256 + threadIdx.x;
    if (i < NN) {
        d_offsets[i] += d_boff[blockIdx.x];
        d_dis[i] = rsqrtf(d_degw[i] + 2.0f);
    }
    if (i == 0) d_offsets[NN] = NE;
}

__global__ void scatter_kernel(const int* __restrict__ ei, const float* __restrict__ ea) {
    int e = blockIdx.x * blockDim.x + threadIdx.x;
    if (e < NE) {
        int src = ei[e], dst = ei[NE + e];
        int pos = d_offsets[dst] + atomicAdd(&d_cursor[dst], 1);
        float ax = ea[2 * e], ay = ea[2 * e + 1];
        float4 pk;
        pk.x = __int_as_float(src);
        pk.y = ax;
        pk.z = ay;
        pk.w = d_dis[src] * ay;
        d_csr[pos] = pk;
    }
}

// ---------------- QKV + skip precompute ---------------------------------------
__global__ void qkv_kernel(const float* __restrict__ x,
                           const float* __restrict__ Wq, const float* __restrict__ bq,
                           const float* __restrict__ Wk, const float* __restrict__ bk,
                           const float* __restrict__ Wv, const float* __restrict__ bv,
                           const float* __restrict__ Wsk, const float* __restrict__ bsk) {
    int lane = threadIdx.x & 31;
    int warp = (blockIdx.x * blockDim.x + threadIdx.x) >> 5;
    int nwarps = (gridDim.x * blockDim.x) >> 5;
    float wq[8], wk[8], wv[8], ws[8];
    #pragma unroll
    for (int i = 0; i < 8; i++) {
        wq[i] = Wq[i * 32 + lane];
        wk[i] = Wk[i * 32 + lane];
        wv[i] = Wv[i * 32 + lane];
        ws[i] = Wsk[i * 32 + lane];
    }
    float bqv = bq[lane], bkv = bk[lane], bvv = bv[lane], bsv = bsk[lane];
    const float QS = 0.25f * 1.4426950408889634f;  // 1/sqrt(16) * log2(e)
    int h = lane >> 4, c = lane & 15;

    for (int n = warp; n < NN; n += nwarps) {
        float x0 = x[n * 64 + lane];
        float x1 = x[n * 64 + 32 + lane];
        #pragma unroll
        for (int b = 0; b < 8; b++) {
            float aq = bqv, ak = bkv, av = bvv, asv = bsv;
            #pragma unroll
            for (int i = 0; i < 8; i++) {
                const int f = b * 8 + i;
                float xv = __shfl_sync(0xffffffffu, (f < 32) ? x0 : x1, f & 31);
                aq += xv * wq[i]; ak += xv * wk[i]; av += xv * wv[i]; asv += xv * ws[i];
            }
            int pairIdx = b * 2 + h;
            d_Qh[n * 256 + pairIdx * 16 + c] = __float2half(aq * QS);
            d_KV[n * 512 + pairIdx * 32 + c]      = __float2half(ak);
            d_KV[n * 512 + pairIdx * 32 + 16 + c] = __float2half(av);
            d_H[n * 256 + pairIdx * 16 + c] = asv;
        }
    }
}

// ---------------- attention ---------------------------------------------------
// ONE warp per dst (independent, no block coupling). Lane owns one (band,head)
// pair; half-warps split edges; 2-edge unroll per half-warp -> 4 in flight.
__device__ __forceinline__ __half2 dot8(uint4 a, uint4 b, const __half2* q) {
    __half2 d = __float2half2_rn(0.f);
    d = __hfma2(q[0], h2(a.x), d);
    d = __hfma2(q[1], h2(a.y), d);
    d = __hfma2(q[2], h2(a.z), d);
    d = __hfma2(q[3], h2(a.w), d);
    d = __hfma2(q[4], h2(b.x), d);
    d = __hfma2(q[5], h2(b.y), d);
    d = __hfma2(q[6], h2(b.z), d);
    d = __hfma2(q[7], h2(b.w), d);
    return d;
}

__global__ void __launch_bounds__(256, 2) attn_kernel(const float* __restrict__ We) {
    int tid = blockIdx.x * blockDim.x + threadIdx.x;
    int dst = tid >> 5;
    if (dst >= NN) return;
    int lane = threadIdx.x & 31;
    int pair = lane & 15, hf = lane >> 4;
    int hoff = (pair & 1) << 4;

    __half2 q[8];
    {
        const uint4* Qp = (const uint4*)&d_Qh[dst * 256 + pair * 16];
        uint4 qa = Qp[0], qb = Qp[1];
        q[0] = h2(qa.x); q[1] = h2(qa.y); q[2] = h2(qa.z); q[3] = h2(qa.w);
        q[4] = h2(qb.x); q[5] = h2(qb.y); q[6] = h2(qb.z); q[7] = h2(qb.w);
    }
    float qw0 = 0.f, qw1 = 0.f;
    #pragma unroll
    for (int i = 0; i < 8; i++) {
        float2 qf = __half22float2(q[i]);
        qw0 += qf.x * We[hoff + 2 * i]      + qf.y * We[hoff + 2 * i + 1];
        qw1 += qf.x * We[32 + hoff + 2 * i] + qf.y * We[32 + hoff + 2 * i + 1];
    }

    __half2 acch[8];
    #pragma unroll
    for (int i = 0; i < 8; i++) acch[i] = __float2half2_rn(0.f);
    float sax = 0.f, say = 0.f, z = 0.f;

    int start = d_offsets[dst], end = d_offsets[dst + 1];
    for (int e = start + hf; e < end; e += 4) {
        int eB = e + 2;
        bool hasB = (eB < end);
        float4 pkA = d_csr[e];
        float4 pkB = d_csr[hasB ? eB : e];
        int srcA = __float_as_int(pkA.x);
        int srcB = __float_as_int(pkB.x);
        const uint4* pA = (const uint4*)&d_KV[srcA * 512 + pair * 32];
        uint4 ka0 = pA[0], ka1 = pA[1], va0 = pA[2], va1 = pA[3];
        const uint4* pB = (const uint4*)&d_KV[srcB * 512 + pair * 32];
        uint4 kb0 = pB[0], kb1 = pB[1], vb0 = pB[2], vb1 = pB[3];

        float2 dA = __half22float2(dot8(ka0, ka1, q));
        float pAf = ex2f(dA.x + dA.y + pkA.y * qw0 + pkA.z * qw1);
        float2 dB = __half22float2(dot8(kb0, kb1, q));
        float pBf = hasB ? ex2f(dB.x + dB.y + pkB.y * qw0 + pkB.z * qw1) : 0.f;

        z += pAf + pBf;
        sax = fmaf(pAf, pkA.y, sax); sax = fmaf(pBf, pkB.y, sax);
        say = fmaf(pAf, pkA.z, say); say = fmaf(pBf, pkB.z, say);

        __half2 pA2 = __float2half2_rn(pAf);
        __half2 pB2 = __float2half2_rn(pBf);
        acch[0] = __hfma2(pA2, h2(va0.x), acch[0]);
        acch[1] = __hfma2(pA2, h2(va0.y), acch[1]);
        acch[2] = __hfma2(pA2, h2(va0.z), acch[2]);
        acch[3] = __hfma2(pA2, h2(va0.w), acch[3]);
        acch[4] = __hfma2(pA2, h2(va1.x), acch[4]);
        acch[5] = __hfma2(pA2, h2(va1.y), acch[5]);
        acch[6] = __hfma2(pA2, h2(va1.z), acch[6]);
        acch[7] = __hfma2(pA2, h2(va1.w), acch[7]);
        acch[0] = __hfma2(pB2, h2(vb0.x), acch[0]);
        acch[1] = __hfma2(pB2, h2(vb0.y), acch[1]);
        acch[2] = __hfma2(pB2, h2(vb0.z), acch[2]);
        acch[3] = __hfma2(pB2, h2(vb0.w), acch[3]);
        acch[4] = __hfma2(pB2, h2(vb1.x), acch[4]);
        acch[5] = __hfma2(pB2, h2(vb1.y), acch[5]);
        acch[6] = __hfma2(pB2, h2(vb1.z), acch[6]);
        acch[7] = __hfma2(pB2, h2(vb1.w), acch[7]);
    }

    float accf[16];
    #pragma unroll
    for (int i = 0; i < 8; i++) {
        float2 t = __half22float2(acch[i]);
        accf[2 * i] = t.x; accf[2 * i + 1] = t.y;
    }
    z   += __shfl_xor_sync(0xffffffffu, z, 16);
    sax += __shfl_xor_sync(0xffffffffu, sax, 16);
    say += __shfl_xor_sync(0xffffffffu, say, 16);
    #pragma unroll
    for (int c = 0; c < 16; c++) accf[c] += __shfl_xor_sync(0xffffffffu, accf[c], 16);

    if (hf == 0) {
        float rz = (z > 0.f) ? 1.0f / z : 0.f;
        float* Hp = &d_H[dst * 256 + pair * 16];
        float o[16];
        #pragma unroll
        for (int c = 0; c < 16; c++) {
            float w0 = We[hoff + c], w1 = We[32 + hoff + c];
            float a = accf[c] + sax * w0 + say * w1;
            float t = fmaf(a, rz, Hp[c]);
            o[c] = (t > 0.f) ? t : 0.1f * (__expf(t) - 1.0f);
        }
        float4* Op = (float4*)Hp;
        Op[0] = make_float4(o[0], o[1], o[2], o[3]);
        Op[1] = make_float4(o[4], o[5], o[6], o[7]);
        Op[2] = make_float4(o[8], o[9], o[10], o[11]);
        Op[3] = make_float4(o[12], o[13], o[14], o[15]);
    }
}

// ---------------- hw = h @ Wg -------------------------------------------------
__global__ void hw_kernel(const float* __restrict__ Wg) {
    __shared__ float wgs[256 * 32];
    for (int idx = threadIdx.x; idx < 8192; idx += blockDim.x)
        wgs[idx] = Wg[idx];
    __syncthreads();
    int lane = threadIdx.x & 31;
    int warp = (blockIdx.x * blockDim.x + threadIdx.x) >> 5;
    int nwarps = (gridDim.x * blockDim.x) >> 5;
    for (int n = warp; n < NN; n += nwarps) {
        const float4* Hp = (const float4*)&d_H[n * 256];
        float a = 0.f;
        #pragma unroll
        for (int c = 0; c < 64; c++) {
            float4 hv = Hp[c];
            a += hv.x * wgs[(4 * c + 0) * 32 + lane];
            a += hv.y * wgs[(4 * c + 1) * 32 + lane];
            a += hv.z * wgs[(4 * c + 2) * 32 + lane];
            a += hv.w * wgs[(4 * c + 3) * 32 + lane];
        }
        d_HW[n * 32 + lane] = a;
    }
}

// ---------------- final normalized propagation --------------------------------
__global__ void final_kernel(const float* __restrict__ bg, float* __restrict__ out) {
    int lane = threadIdx.x & 31;
    int dst = (blockIdx.x * blockDim.x + threadIdx.x) >> 5;
    if (dst >= NN) return;
    float dd = d_dis[dst];
    float acc = 2.0f * dd * d_HW[dst * 32 + lane];  // self loop
    int start = d_offsets[dst], end = d_offsets[dst + 1];
    int t = start;
    for (; t + 1 < end; t += 2) {
        float4 a = d_csr[t];
        float4 b = d_csr[t + 1];
        float va = d_HW[__float_as_int(a.x) * 32 + lane];
        float vb = d_HW[__float_as_int(b.x) * 32 + lane];
        acc = fmaf(a.w, va, acc);
        acc = fmaf(b.w, vb, acc);
    }
    if (t < end) {
        float4 a = d_csr[t];
        acc = fmaf(a.w, d_HW[__float_as_int(a.x) * 32 + lane], acc);
    }
    out[dst * 32 + lane] = bg[lane] + dd * acc;
}

// ---------------- launch -----------------------------------------------------
extern "C" void kernel_launch(void* const* d_in, const int* in_sizes, int n_in,
                              void* d_out, int out_size) {
    const float* x   = (const float*)d_in[0];
    const float* ea  = (const float*)d_in[1];
    const float* Wq  = (const float*)d_in[2];
    const float* bq  = (const float*)d_in[3];
    const float* Wk  = (const float*)d_in[4];
    const float* bk  = (const float*)d_in[5];
    const float* Wv  = (const float*)d_in[6];
    const float* bv  = (const float*)d_in[7];
    const float* We  = (const float*)d_in[8];
    const float* Wsk = (const float*)d_in[9];
    const float* bsk = (const float*)d_in[10];
    const float* Wg  = (const float*)d_in[11];
    const float* bg  = (const float*)d_in[12];
    const int*   ei  = (const int*)d_in[13];
    float* out = (float*)d_out;

    zero_kernel<<<(NN + 255) / 256, 256>>>();
    hist_kernel<<<(NE + 255) / 256, 256>>>(ei, ea);
    scanA_kernel<<<NB, 256>>>();
    scanB_kernel<<<1, 256>>>();
    scanC_kernel<<<NB, 256>>>();
    scatter_kernel<<<(NE + 255) / 256, 256>>>(ei, ea);
    qkv_kernel<<<400, 256>>>(x, Wq, bq, Wk, bk, Wv, bv, Wsk, bsk);
    attn_kernel<<<(NN * 32 + 255) / 256, 256>>>(We);
    hw_kernel<<<296, 256>>>(Wg);
    final_kernel<<<(NN * 32 + 255) / 256, 256>>>(bg, out);
}